// round 8
// baseline (speedup 1.0000x reference)
#include <cuda_runtime.h>

#define NPED    4096
#define NBLK    1024
#define NTHR    128

#define DT        0.4f
#define K_ATTR    2.0f
#define PED_SPEED 1.0f
#define INV_MASS  (1.0f/60.0f)
#define EPS       1e-8f
#define A_COST    5.0f
#define B_COST    2.0f
// 10*exp((0.6-dist)/0.71) = exp2(C1 - dist*C2)
#define C2_EXP 2.0319648f
#define C1_EXP 4.5411053f

__device__ unsigned int g_ticket = 0;          // reset by last block each launch
__device__ float g_dev_part[NBLK];

__device__ __forceinline__ float ex2_approx(float x) {
    float r; asm("ex2.approx.f32 %0, %1;" : "=f"(r) : "f"(x)); return r;
}
__device__ __forceinline__ float rsqrt_approx(float x) {
    float r; asm("rsqrt.approx.f32 %0, %1;" : "=f"(r) : "f"(x)); return r;
}

// Single fused kernel: stacked copy + forces + propagation + cost.
// 1024 blocks x 128 threads; warp w of block b owns pedestrian i = b*4 + w.
__global__ void __launch_bounds__(NTHR) fused_kernel(
    const float* __restrict__ state,       // [N,4]
    const float* __restrict__ goal,        // [N,2]
    const float* __restrict__ stacked_in,  // [N*4]
    const float* __restrict__ observed,    // [N,4]
    const float* __restrict__ cost_in,     // [1]
    float* __restrict__ out_state,         // [N,4]
    float* __restrict__ out_cost,          // [1]
    float* __restrict__ out_stacked)       // [2*N*4] (4B-aligned only)
{
    __shared__ float2 sneg[NPED];          // negated positions, 32KB
    __shared__ float  s_dev[4];
    __shared__ int    s_last;
    __shared__ float  s_red[8];

    const int tid  = threadIdx.x;
    const int lane = tid & 31;
    const int w    = tid >> 5;
    const int i    = blockIdx.x * 4 + w;

    // fused concat copy: g in [0, 16384) -> blocks 0..127 cover both halves
    {
        int g = blockIdx.x * NTHR + tid;
        if (g < NPED * 4) {
            out_stacked[g]            = stacked_in[g];
            out_stacked[NPED * 4 + g] = state[g];
        }
    }

    // stage negated positions in smem
    const float2* __restrict__ pos2 = (const float2*)state;  // row = {pos, vel}
    #pragma unroll
    for (int k = tid; k < NPED; k += NTHR) {
        float2 p = pos2[k * 2];
        sneg[k] = make_float2(-p.x, -p.y);
    }
    __syncthreads();

    // own row
    const float4 si = ((const float4*)state)[i];
    const float xi = si.x, yi = si.y;

    unsigned long long xy;
    asm("mov.b64 %0, {%1, %2};" : "=l"(xy) : "f"(xi), "f"(yi));

    unsigned long long facc = 0ull;   // packed {fx, fy}
    const unsigned long long* __restrict__ su = (const unsigned long long*)sneg;

    #pragma unroll 8
    for (int jj = lane; jj < NPED; jj += 32) {
        unsigned long long lj = su[jj];               // LDS.64
        unsigned long long pd;
        asm("add.rn.f32x2 %0, %1, %2;" : "=l"(pd) : "l"(xy), "l"(lj)); // {dx,dy}
        float dx, dy;
        asm("mov.b64 {%0, %1}, %2;" : "=f"(dx), "=f"(dy) : "l"(pd));
        float d2 = fmaf(dx, dx, fmaf(dy, dy, EPS));
        float rd = rsqrt_approx(d2);
        float dist = d2 * rd;
        float coef = ex2_approx(fmaf(dist, -C2_EXP, C1_EXP)) * rd;
        // j==i: dx=dy=0 exactly -> contribution exactly 0
        unsigned long long c2;
        asm("mov.b64 %0, {%1, %1};" : "=l"(c2) : "f"(coef));
        asm("fma.rn.f32x2 %0, %1, %2, %0;" : "+l"(facc) : "l"(pd), "l"(c2));
    }

    float fx, fy;
    asm("mov.b64 {%0, %1}, %2;" : "=f"(fx), "=f"(fy) : "l"(facc));

    // warp reduction
    #pragma unroll
    for (int o = 16; o > 0; o >>= 1) {
        fx += __shfl_xor_sync(0xffffffffu, fx, o);
        fy += __shfl_xor_sync(0xffffffffu, fy, o);
    }

    if (lane == 0) {
        const float vx = si.z, vy = si.w;
        const float2 gl = ((const float2*)goal)[i];

        float tgx = gl.x - xi, tgy = gl.y - yi;
        float dg2 = fmaf(tgx, tgx, fmaf(tgy, tgy, EPS));
        float rdg = rsqrt_approx(dg2);
        float afx = K_ATTR * fmaf(PED_SPEED * tgx, rdg, -vx);
        float afy = K_ATTR * fmaf(PED_SPEED * tgy, rdg, -vy);

        float Fx = fmaf(fx, INV_MASS, afx);
        float Fy = fmaf(fy, INV_MASS, afy);

        float npx = xi + vx * DT + 0.5f * Fx * (DT * DT);
        float npy = yi + vy * DT + 0.5f * Fy * (DT * DT);
        float nvx = fmaf(Fx, DT, vx);
        float nvy = fmaf(Fy, DT, vy);
        float spd = sqrtf(fmaf(nvx, nvx, fmaf(nvy, nvy, EPS)));
        float scale = fminf(1.0f, PED_SPEED / spd);

        float4 outrow = make_float4(npx, npy, nvx * scale, nvy * scale);
        ((float4*)out_state)[i] = outrow;

        // local deviation contribution (peds = rows 1..N-1)
        float dev = 0.0f;
        if (i > 0) {
            float ox = observed[i*4 + 0];
            float oy = observed[i*4 + 1];
            float ddx = npx - ox, ddy = npy - oy;
            dev = sqrtf(fmaf(ddx, ddx, fmaf(ddy, ddy, EPS)));
        }
        s_dev[w] = dev;
    }
    __syncthreads();

    if (tid == 0)
        g_dev_part[blockIdx.x] = s_dev[0] + s_dev[1] + s_dev[2] + s_dev[3];

    // make all global writes of this block visible, then take a ticket
    __threadfence();
    if (tid == 0) {
        unsigned int t = atomicAdd(&g_ticket, 1u);
        s_last = (t == NBLK - 1) ? 1 : 0;
    }
    __syncthreads();

    // ---- last block finalizes the cost ----
    if (s_last) {
        __threadfence();
        const float rx = __ldcg(&out_state[0]);
        const float ry = __ldcg(&out_state[1]);

        // deterministic sum of per-block deviation partials
        float dev = 0.0f;
        #pragma unroll
        for (int k = 0; k < NBLK / NTHR; k++)
            dev += __ldcg(&g_dev_part[tid + k * NTHR]);

        // blame over peds 1..N-1
        float blm = 0.0f;
        for (int p = 1 + tid; p < NPED; p += NTHR) {
            float2 pp = __ldcg((const float2*)(out_state + p * 4));
            float bx = pp.x - rx, by = pp.y - ry;
            float d = sqrtf(fmaf(bx, bx, fmaf(by, by, EPS)));
            blm += ex2_approx(-d * 1.4426950f);   // exp(-d), E_COST=1
        }

        #pragma unroll
        for (int o = 16; o > 0; o >>= 1) {
            dev += __shfl_xor_sync(0xffffffffu, dev, o);
            blm += __shfl_xor_sync(0xffffffffu, blm, o);
        }
        if (lane == 0) { s_red[w] = dev; s_red[4 + w] = blm; }
        __syncthreads();

        if (tid == 0) {
            float devt = s_red[0] + s_red[1] + s_red[2] + s_red[3];
            float blmt = s_red[4] + s_red[5] + s_red[6] + s_red[7];
            float ix = state[0], iy = state[1];
            float gx = goal[0],  gy = goal[1];
            float d1x = ix - gx, d1y = iy - gy;
            float d2x = rx - gx, d2y = ry - gy;
            float pg = sqrtf(fmaf(d1x, d1x, fmaf(d1y, d1y, EPS)))
                     - sqrtf(fmaf(d2x, d2x, fmaf(d2y, d2y, EPS)));
            out_cost[0] = cost_in[0] + A_COST * devt + B_COST * blmt - pg;
            g_ticket = 0;   // reset for next graph replay
            __threadfence();
        }
    }
}

extern "C" void kernel_launch(void* const* d_in, const int* in_sizes, int n_in,
                              void* d_out, int out_size) {
    const float* state      = (const float*)d_in[0];
    const float* cost_in    = (const float*)d_in[1];
    const float* stacked_in = (const float*)d_in[2];
    const float* goal       = (const float*)d_in[3];
    const float* observed   = (const float*)d_in[4];

    float* out = (float*)d_out;
    float* out_state   = out;
    float* out_cost    = out + NPED*4;
    float* out_stacked = out + NPED*4 + 1;

    fused_kernel<<<NBLK, NTHR>>>(state, goal, stacked_in, observed, cost_in,
                                 out_state, out_cost, out_stacked);
}

// round 9
// speedup vs baseline: 1.2575x; 1.2575x over previous
#include <cuda_runtime.h>

#define NPED    4096
#define NBLK    512
#define NTHR    256

#define DT        0.4f
#define K_ATTR    2.0f
#define PED_SPEED 1.0f
#define INV_MASS  (1.0f/60.0f)
#define EPS       1e-8f
#define A_COST    5.0f
#define B_COST    2.0f
// 10*exp((0.6-dist)/0.71) = exp2(C1 - dist*C2)
#define C2_EXP 2.0319648f
#define C1_EXP 4.5411053f

__device__ unsigned int g_ticket = 0;       // reset by last block each launch
__device__ float g_dev_part[NBLK];

__device__ __forceinline__ float ex2_approx(float x) {
    float r; asm("ex2.approx.f32 %0, %1;" : "=f"(r) : "f"(x)); return r;
}
__device__ __forceinline__ float rsqrt_approx(float x) {
    float r; asm("rsqrt.approx.f32 %0, %1;" : "=f"(r) : "f"(x)); return r;
}

// Single fused kernel: stacked copy + forces + propagation + cost.
// 512 blocks x 256 threads; warp w of block b owns pedestrian i = b*8 + w.
__global__ void __launch_bounds__(NTHR) fused_kernel(
    const float* __restrict__ state,       // [N,4]
    const float* __restrict__ goal,        // [N,2]
    const float* __restrict__ stacked_in,  // [N*4]
    const float* __restrict__ observed,    // [N,4]
    const float* __restrict__ cost_in,     // [1]
    float* __restrict__ out_state,         // [N,4]
    float* __restrict__ out_cost,          // [1]
    float* __restrict__ out_stacked)       // [2*N*4] (4B-aligned only)
{
    __shared__ float2 spos[NPED];          // 32KB: all positions
    __shared__ float  s_dev[8];
    __shared__ int    s_last;
    __shared__ float  s_red[16];

    const int tid  = threadIdx.x;
    const int lane = tid & 31;
    const int w    = tid >> 5;
    const int i    = blockIdx.x * 8 + w;

    // fused concat copy: g in [0, 16384) -> blocks 0..63 cover both halves
    {
        int g = blockIdx.x * NTHR + tid;
        if (g < NPED * 4) {
            out_stacked[g]            = stacked_in[g];
            out_stacked[NPED * 4 + g] = state[g];
        }
    }

    // stage positions in smem (one shot, one barrier)
    const float2* __restrict__ pos2 = (const float2*)state;  // row = {pos, vel}
    #pragma unroll
    for (int k = tid; k < NPED; k += NTHR)
        spos[k] = pos2[k * 2];
    __syncthreads();

    // own row
    const float4 si = ((const float4*)state)[i];
    const float xi = si.x, yi = si.y;

    float fx = 0.0f, fy = 0.0f;

    #pragma unroll 8
    for (int jj = lane; jj < NPED; jj += 32) {
        float2 pj = spos[jj];
        float dx = xi - pj.x;
        float dy = yi - pj.y;
        float d2 = fmaf(dx, dx, fmaf(dy, dy, EPS));
        float rd = rsqrt_approx(d2);
        float dist = d2 * rd;                                   // sqrt(d2)
        float coef = ex2_approx(fmaf(dist, -C2_EXP, C1_EXP)) * rd;
        // j==i: dx=dy=0 exactly -> contributes exactly 0
        fx = fmaf(coef, dx, fx);
        fy = fmaf(coef, dy, fy);
    }

    // warp reduction
    #pragma unroll
    for (int o = 16; o > 0; o >>= 1) {
        fx += __shfl_xor_sync(0xffffffffu, fx, o);
        fy += __shfl_xor_sync(0xffffffffu, fy, o);
    }

    if (lane == 0) {
        const float vx = si.z, vy = si.w;
        const float2 gl = ((const float2*)goal)[i];

        float tgx = gl.x - xi, tgy = gl.y - yi;
        float dg2 = fmaf(tgx, tgx, fmaf(tgy, tgy, EPS));
        float rdg = rsqrt_approx(dg2);
        float afx = K_ATTR * fmaf(PED_SPEED * tgx, rdg, -vx);
        float afy = K_ATTR * fmaf(PED_SPEED * tgy, rdg, -vy);

        float Fx = fmaf(fx, INV_MASS, afx);
        float Fy = fmaf(fy, INV_MASS, afy);

        float npx = xi + vx * DT + 0.5f * Fx * (DT * DT);
        float npy = yi + vy * DT + 0.5f * Fy * (DT * DT);
        float nvx = fmaf(Fx, DT, vx);
        float nvy = fmaf(Fy, DT, vy);
        float spd = sqrtf(fmaf(nvx, nvx, fmaf(nvy, nvy, EPS)));
        float scale = fminf(1.0f, PED_SPEED / spd);

        ((float4*)out_state)[i] = make_float4(npx, npy, nvx * scale, nvy * scale);

        // local deviation contribution (peds = rows 1..N-1)
        float dev = 0.0f;
        if (i > 0) {
            float ox = observed[i*4 + 0];
            float oy = observed[i*4 + 1];
            float ddx = npx - ox, ddy = npy - oy;
            dev = sqrtf(fmaf(ddx, ddx, fmaf(ddy, ddy, EPS)));
        }
        s_dev[w] = dev;
    }
    __syncthreads();

    if (tid == 0) {
        float d = 0.0f;
        #pragma unroll
        for (int k = 0; k < 8; k++) d += s_dev[k];
        g_dev_part[blockIdx.x] = d;
    }

    // make this block's global writes visible, then take a ticket
    __threadfence();
    if (tid == 0) {
        unsigned int t = atomicAdd(&g_ticket, 1u);
        s_last = (t == NBLK - 1) ? 1 : 0;
    }
    __syncthreads();

    // ---- last block finalizes the cost ----
    if (s_last) {
        __threadfence();
        const float rx = __ldcg(&out_state[0]);
        const float ry = __ldcg(&out_state[1]);

        // deterministic sum of per-block deviation partials
        float dev = 0.0f;
        #pragma unroll
        for (int k = 0; k < NBLK / NTHR; k++)
            dev += __ldcg(&g_dev_part[tid + k * NTHR]);

        // blame over peds 1..N-1
        float blm = 0.0f;
        for (int p = 1 + tid; p < NPED; p += NTHR) {
            float2 pp = __ldcg((const float2*)(out_state + p * 4));
            float bx = pp.x - rx, by = pp.y - ry;
            float d = sqrtf(fmaf(bx, bx, fmaf(by, by, EPS)));
            blm += ex2_approx(-d * 1.4426950f);   // exp(-d), E_COST=1
        }

        #pragma unroll
        for (int o = 16; o > 0; o >>= 1) {
            dev += __shfl_xor_sync(0xffffffffu, dev, o);
            blm += __shfl_xor_sync(0xffffffffu, blm, o);
        }
        if (lane == 0) { s_red[w] = dev; s_red[8 + w] = blm; }
        __syncthreads();

        if (tid == 0) {
            float devt = 0.0f, blmt = 0.0f;
            #pragma unroll
            for (int k = 0; k < 8; k++) { devt += s_red[k]; blmt += s_red[8 + k]; }
            float ix = state[0], iy = state[1];
            float gx = goal[0],  gy = goal[1];
            float d1x = ix - gx, d1y = iy - gy;
            float d2x = rx - gx, d2y = ry - gy;
            float pg = sqrtf(fmaf(d1x, d1x, fmaf(d1y, d1y, EPS)))
                     - sqrtf(fmaf(d2x, d2x, fmaf(d2y, d2y, EPS)));
            out_cost[0] = cost_in[0] + A_COST * devt + B_COST * blmt - pg;
            g_ticket = 0;   // reset for next graph replay
            __threadfence();
        }
    }
}

extern "C" void kernel_launch(void* const* d_in, const int* in_sizes, int n_in,
                              void* d_out, int out_size) {
    const float* state      = (const float*)d_in[0];
    const float* cost_in    = (const float*)d_in[1];
    const float* stacked_in = (const float*)d_in[2];
    const float* goal       = (const float*)d_in[3];
    const float* observed   = (const float*)d_in[4];

    float* out = (float*)d_out;
    float* out_state   = out;
    float* out_cost    = out + NPED*4;
    float* out_stacked = out + NPED*4 + 1;

    fused_kernel<<<NBLK, NTHR>>>(state, goal, stacked_in, observed, cost_in,
                                 out_state, out_cost, out_stacked);
}